// round 4
// baseline (speedup 1.0000x reference)
#include <cuda_runtime.h>
#include <cstdint>

// Problem dims (fixed by dataset)
#define BB 8
#define CC 96
#define GG 64   // PY*PX = 8*8
#define JJ 17
#define KK 96
#define KT 8                  // k-values per thread-item in phase B
#define KTILES (KK / KT)      // 12
#define NGROUPS (JJ * KTILES) // 204
#define NTHR 128
#define WIDTH_F 128.0f
#define LOG2E 1.4426950408889634f

// Output layout: concat(oks_parts_sel [B,C,G,J], oks_person_sel [B,C,G], pose_gt [B,C,J,3])
#define PARTS_SZ  (BB*CC*GG*JJ)
#define PERSON_SZ (BB*CC*GG)
#define PERSON_OFF PARTS_SZ
#define POSE_OFF  (PARTS_SZ + PERSON_SZ)

__device__ __forceinline__ float fast_ex2(float x) {
    float y;
    asm("ex2.approx.ftz.f32 %0, %1;" : "=f"(y) : "f"(x));
    return y;
}

__device__ __forceinline__ unsigned long long pack_f32x2(float lo, float hi) {
    unsigned long long r;
    asm("mov.b64 %0, {%1, %2};" : "=l"(r) : "f"(lo), "f"(hi));
    return r;
}

__device__ __forceinline__ unsigned long long add_f32x2(unsigned long long a, unsigned long long b) {
    unsigned long long r;
    asm("add.rn.f32x2 %0, %1, %2;" : "=l"(r) : "l"(a), "l"(b));
    return r;
}

__device__ __forceinline__ float2 unpack_f32x2(unsigned long long v) {
    float2 f;
    asm("mov.b64 {%0, %1}, %2;" : "=f"(f.x), "=f"(f.y) : "l"(v));
    return f;
}

__global__ __launch_bounds__(NTHR, 6)
void oks_assign_kernel(
    const float* __restrict__ pose_pool,   // [B,C,8,8,J,2]
    const float* __restrict__ keypoints,   // [B,K,J,3]
    const float* __restrict__ areas,       // [B,K]
    const float* __restrict__ transforms,  // [B,3,3]
    const float* __restrict__ tinv,        // [B,3,3]
    const int*   __restrict__ hflip,       // [B]
    const float* __restrict__ sigmas,      // [J]
    float* __restrict__ out)
{
    const int c = blockIdx.x;
    const int b = blockIdx.y;
    const int tid = threadIdx.x;

    __shared__ float2 s_xy[JJ][GG + 1];  // (x,y) image coords, padded row
    __shared__ float s_val[KK * JJ];     // phase B: best-per-(k,j); phase D: oks[g][j]
    __shared__ float s_score[KK];
    __shared__ float s_ivs[KK];          // 1 / clip(vis_sum,1)
    __shared__ float s_sig[JJ];
    __shared__ int   s_kstar;

    if (tid < JJ) s_sig[tid] = sigmas[tid];

    const float ti00 = tinv[b*9+0], ti01 = tinv[b*9+1], ti02 = tinv[b*9+2];
    const float ti10 = tinv[b*9+3], ti11 = tinv[b*9+4], ti12 = tinv[b*9+5];
    const bool flip = hflip[b] > 0;

    // ---- Phase A: pool -> image coordinates into SMEM [j][g] as float2 ----
    const float* pp = pose_pool + (size_t)(b*CC + c) * GG * JJ * 2;
    for (int idx = tid; idx < GG*JJ; idx += NTHR) {
        int g = idx / JJ, j = idx - g*JJ;
        float x0 = pp[idx*2 + 0];
        float y0 = pp[idx*2 + 1];
        float fx = flip ? (WIDTH_F - 1.0f - x0) : x0;
        float xi = fx*ti00 + y0*ti01 + ti02;
        float yi = fx*ti10 + y0*ti11 + ti12;
        s_xy[j][g] = make_float2(xi, yi);
    }

    // ---- vis_sum per k ----
    const float* kpt = keypoints + (size_t)b * KK * JJ * 3;
    for (int k = tid; k < KK; k += NTHR) {
        float vs = 0.f;
        #pragma unroll
        for (int j = 0; j < JJ; j++)
            vs += (kpt[(k*JJ + j)*3 + 2] > 0.f) ? 1.0f : 0.0f;
        s_ivs[k] = 1.0f / fmaxf(vs, 1.0f);
    }
    __syncthreads();

    // ---- Phase B: per (k,j) min over grid of d^2, one ex2 at the end ----
    // max_g exp(scale*d2) == exp(scale * min_g d2) since scale < 0 and ex2 monotone.
    for (int item = tid; item < NGROUPS; item += NTHR) {
        const int j  = item % JJ;
        const int k0 = (item / JJ) * KT;

        unsigned long long nk[KT];   // packed (-kx, -ky)
        float md[KT];
        #pragma unroll
        for (int kk = 0; kk < KT; kk++) {
            const float* kp = kpt + ((k0 + kk)*JJ + j)*3;
            nk[kk] = pack_f32x2(-kp[0], -kp[1]);
            md[kk] = 3.4e38f;
        }

        const float2* row = s_xy[j];
        #pragma unroll 4
        for (int g = 0; g < GG; g++) {
            unsigned long long c64 =
                *reinterpret_cast<const unsigned long long*>(&row[g]);
            #pragma unroll
            for (int kk = 0; kk < KT; kk++) {
                float2 d = unpack_f32x2(add_f32x2(c64, nk[kk]));
                float d2 = fmaf(d.x, d.x, d.y*d.y);
                md[kk] = fminf(md[kk], d2);
            }
        }

        const float sg = 2.0f * s_sig[j];
        #pragma unroll
        for (int kk = 0; kk < KT; kk++) {
            const int k = k0 + kk;
            float v = kpt[(k*JJ + j)*3 + 2];
            float val = 0.0f;
            if (v > 0.0f) {
                float denom = fmaxf(2.0f * sg * sg * areas[b*KK + k], 1e-6f);
                val = fast_ex2(md[kk] * (-LOG2E / denom));
            }
            s_val[k*JJ + j] = val;
        }
    }
    __syncthreads();

    // ---- Phase B2: per-k score ----
    for (int k = tid; k < KK; k += NTHR) {
        float s = 0.f;
        #pragma unroll
        for (int j = 0; j < JJ; j++) s += s_val[k*JJ + j];
        s_score[k] = s * s_ivs[k];
    }
    __syncthreads();

    // ---- Phase C: warp-parallel argmax (first-max semantics) ----
    // Global first-max == (max score, smallest k among exact maxima).
    if (tid < 32) {
        float bs = -1.0f; int bi = 0;
        #pragma unroll
        for (int p = 0; p < KK/32; p++) {
            int k = tid + p*32;                 // ascending k within lane
            float sc = s_score[k];
            if (sc > bs) { bs = sc; bi = k; }   // strictly greater keeps smallest k
        }
        #pragma unroll
        for (int off = 16; off > 0; off >>= 1) {
            float os = __shfl_xor_sync(0xffffffffu, bs, off);
            int   oi = __shfl_xor_sync(0xffffffffu, bi, off);
            if (os > bs || (os == bs && oi < bi)) { bs = os; bi = oi; }
        }
        if (tid == 0) s_kstar = bi;
    }
    __syncthreads();
    const int ks = s_kstar;
    const float area_ks = areas[b*KK + ks];

    // ---- Phase D: OKS map for k* into s_val[g][j] ----
    for (int item = tid; item < GG*JJ; item += NTHR) {
        int j = item / GG, g = item - j*GG;
        float kx = kpt[(ks*JJ + j)*3 + 0];
        float ky = kpt[(ks*JJ + j)*3 + 1];
        float v  = kpt[(ks*JJ + j)*3 + 2];
        float o = 0.0f;
        if (v > 0.0f) {
            float sg = 2.0f * s_sig[j];
            float denom = fmaxf(2.0f * sg * sg * area_ks, 1e-6f);
            float scale = -LOG2E / denom;
            float2 cxy = s_xy[j][g];
            float dx = cxy.x - kx;
            float dy = cxy.y - ky;
            o = fast_ex2(fmaf(dx, dx, dy*dy) * scale);
        }
        s_val[g*JJ + j] = o;
    }
    __syncthreads();

    // ---- Phase E: emit outputs ----
    float* parts = out + (size_t)(b*CC + c) * GG * JJ;
    for (int idx = tid; idx < GG*JJ; idx += NTHR) parts[idx] = s_val[idx];

    float* person = out + PERSON_OFF + (size_t)(b*CC + c) * GG;
    const float ivs_ks = s_ivs[ks];
    for (int g = tid; g < GG; g += NTHR) {
        float s = 0.f;
        #pragma unroll
        for (int j = 0; j < JJ; j++) s += s_val[g*JJ + j];
        person[g] = s * ivs_ks;
    }

    if (tid < JJ) {
        int j = tid;
        float X = kpt[(ks*JJ + j)*3 + 0];
        float Y = kpt[(ks*JJ + j)*3 + 1];
        float V = kpt[(ks*JJ + j)*3 + 2];
        float t00 = transforms[b*9+0], t01 = transforms[b*9+1], t02 = transforms[b*9+2];
        float t10 = transforms[b*9+3], t11 = transforms[b*9+4], t12 = transforms[b*9+5];
        float gx = t00*X + t01*Y + t02;
        float gy = t10*X + t11*Y + t12;
        if (flip) gx = WIDTH_F - 1.0f - gx;
        float sg = 2.0f * s_sig[j];
        float gv = (V > 0.f) ? (t00 * t11) * (area_ks * sg * sg) : 0.0f;
        float* pg = out + POSE_OFF + (size_t)((b*CC + c)*JJ + j) * 3;
        pg[0] = gx; pg[1] = gy; pg[2] = gv;
    }
}

extern "C" void kernel_launch(void* const* d_in, const int* in_sizes, int n_in,
                              void* d_out, int out_size) {
    const float* pose_pool  = (const float*)d_in[0];
    const float* keypoints  = (const float*)d_in[1];
    const float* areas      = (const float*)d_in[2];
    const float* transforms = (const float*)d_in[3];
    const float* tinv       = (const float*)d_in[4];
    const int*   hflip      = (const int*)  d_in[5];
    const float* sigmas     = (const float*)d_in[6];
    float* out = (float*)d_out;

    dim3 grid(CC, BB);
    oks_assign_kernel<<<grid, NTHR>>>(pose_pool, keypoints, areas, transforms,
                                      tinv, hflip, sigmas, out);
}

// round 6
// speedup vs baseline: 1.1156x; 1.1156x over previous
#include <cuda_runtime.h>
#include <cstdint>

// Problem dims (fixed by dataset)
#define BB 8
#define CC 96
#define GG 64   // PY*PX = 8*8
#define JJ 17
#define KK 96
#define KT 4                  // k-values per thread-item in phase B
#define KTILES (KK / KT)      // 24
#define NGROUPS (JJ * KTILES) // 408
#define NTHR 256
#define WIDTH_F 128.0f
#define LOG2E 1.4426950408889634f

// Output layout: concat(oks_parts_sel [B,C,G,J], oks_person_sel [B,C,G], pose_gt [B,C,J,3])
#define PARTS_SZ  (BB*CC*GG*JJ)
#define PERSON_SZ (BB*CC*GG)
#define PERSON_OFF PARTS_SZ
#define POSE_OFF  (PARTS_SZ + PERSON_SZ)

__device__ __forceinline__ float fast_ex2(float x) {
    float y;
    asm("ex2.approx.ftz.f32 %0, %1;" : "=f"(y) : "f"(x));
    return y;
}

__device__ __forceinline__ unsigned long long pack_f32x2(float lo, float hi) {
    unsigned long long r;
    asm("mov.b64 %0, {%1, %2};" : "=l"(r) : "f"(lo), "f"(hi));
    return r;
}

__device__ __forceinline__ unsigned long long add_f32x2(unsigned long long a, unsigned long long b) {
    unsigned long long r;
    asm("add.rn.f32x2 %0, %1, %2;" : "=l"(r) : "l"(a), "l"(b));
    return r;
}

__device__ __forceinline__ float2 unpack_f32x2(unsigned long long v) {
    float2 f;
    asm("mov.b64 {%0, %1}, %2;" : "=f"(f.x), "=f"(f.y) : "l"(v));
    return f;
}

__global__ __launch_bounds__(NTHR, 5)
void oks_assign_kernel(
    const float* __restrict__ pose_pool,   // [B,C,8,8,J,2]
    const float* __restrict__ keypoints,   // [B,K,J,3]
    const float* __restrict__ areas,       // [B,K]
    const float* __restrict__ transforms,  // [B,3,3]
    const float* __restrict__ tinv,        // [B,3,3]
    const int*   __restrict__ hflip,       // [B]
    const float* __restrict__ sigmas,      // [J]
    float* __restrict__ out)
{
    const int c = blockIdx.x;
    const int b = blockIdx.y;
    const int tid = threadIdx.x;

    __shared__ float2 s_xy[JJ][GG + 1];              // (x,y) image coords, padded row
    __shared__ __align__(16) float s_val[KK * JJ];   // 16B-aligned for float4 stores
    __shared__ float s_score[KK];
    __shared__ float s_ivs[KK];                       // 1 / clip(vis_sum,1)
    __shared__ float s_sig[JJ];
    __shared__ int   s_kstar;

    if (tid < JJ) s_sig[tid] = sigmas[tid];

    const float ti00 = tinv[b*9+0], ti01 = tinv[b*9+1], ti02 = tinv[b*9+2];
    const float ti10 = tinv[b*9+3], ti11 = tinv[b*9+4], ti12 = tinv[b*9+5];
    const bool flip = hflip[b] > 0;

    // ---- Phase A: pool -> image coordinates into SMEM [j][g] (float2 loads) ----
    const float2* pp = (const float2*)(pose_pool + (size_t)(b*CC + c) * GG * JJ * 2);
    for (int idx = tid; idx < GG*JJ; idx += NTHR) {
        int g = idx / JJ, j = idx - g*JJ;
        float2 p = pp[idx];
        float fx = flip ? (WIDTH_F - 1.0f - p.x) : p.x;
        float xi = fx*ti00 + p.y*ti01 + ti02;
        float yi = fx*ti10 + p.y*ti11 + ti12;
        s_xy[j][g] = make_float2(xi, yi);
    }

    // ---- vis_sum per k ----
    const float* kpt = keypoints + (size_t)b * KK * JJ * 3;
    for (int k = tid; k < KK; k += NTHR) {
        float vs = 0.f;
        #pragma unroll
        for (int j = 0; j < JJ; j++)
            vs += (kpt[(k*JJ + j)*3 + 2] > 0.f) ? 1.0f : 0.0f;
        s_ivs[k] = 1.0f / fmaxf(vs, 1.0f);
    }
    __syncthreads();

    // ---- Phase B: per (k,j) min over grid of d^2, one ex2 at the end ----
    // max_g exp(scale*d2) == exp(scale * min_g d2) since scale < 0 and ex2 monotone.
    for (int item = tid; item < NGROUPS; item += NTHR) {
        const int j  = item % JJ;
        const int k0 = (item / JJ) * KT;

        unsigned long long nk[KT];   // packed (-kx, -ky)
        float md[KT];
        #pragma unroll
        for (int kk = 0; kk < KT; kk++) {
            const float* kp = kpt + ((k0 + kk)*JJ + j)*3;
            nk[kk] = pack_f32x2(-kp[0], -kp[1]);
            md[kk] = 3.4e38f;
        }

        const float2* row = s_xy[j];
        #pragma unroll 8
        for (int g = 0; g < GG; g++) {
            unsigned long long c64 =
                *reinterpret_cast<const unsigned long long*>(&row[g]);
            #pragma unroll
            for (int kk = 0; kk < KT; kk++) {
                float2 d = unpack_f32x2(add_f32x2(c64, nk[kk]));
                float d2 = fmaf(d.x, d.x, d.y*d.y);
                md[kk] = fminf(md[kk], d2);
            }
        }

        const float sg = 2.0f * s_sig[j];
        #pragma unroll
        for (int kk = 0; kk < KT; kk++) {
            const int k = k0 + kk;
            float v = kpt[(k*JJ + j)*3 + 2];
            float val = 0.0f;
            if (v > 0.0f) {
                float denom = fmaxf(2.0f * sg * sg * areas[b*KK + k], 1e-6f);
                val = fast_ex2(md[kk] * (-LOG2E / denom));
            }
            s_val[k*JJ + j] = val;
        }
    }
    __syncthreads();

    // ---- Phase B2: per-k score (deterministic order) ----
    for (int k = tid; k < KK; k += NTHR) {
        float s = 0.f;
        #pragma unroll
        for (int j = 0; j < JJ; j++) s += s_val[k*JJ + j];
        s_score[k] = s * s_ivs[k];
    }
    __syncthreads();

    // ---- Phase C: warp-parallel argmax (first-max semantics) ----
    if (tid < 32) {
        float bs = -1.0f; int bi = 0;
        #pragma unroll
        for (int p = 0; p < KK/32; p++) {
            int k = tid + p*32;                 // ascending k within lane
            float sc = s_score[k];
            if (sc > bs) { bs = sc; bi = k; }   // strictly greater keeps smallest k
        }
        #pragma unroll
        for (int off = 16; off > 0; off >>= 1) {
            float os = __shfl_xor_sync(0xffffffffu, bs, off);
            int   oi = __shfl_xor_sync(0xffffffffu, bi, off);
            if (os > bs || (os == bs && oi < bi)) { bs = os; bi = oi; }
        }
        if (tid == 0) s_kstar = bi;
    }
    __syncthreads();
    const int ks = s_kstar;
    const float area_ks = areas[b*KK + ks];

    // ---- Phase D: OKS map for k* into s_val[g][j] ----
    for (int item = tid; item < GG*JJ; item += NTHR) {
        int j = item / GG, g = item - j*GG;
        float kx = kpt[(ks*JJ + j)*3 + 0];
        float ky = kpt[(ks*JJ + j)*3 + 1];
        float v  = kpt[(ks*JJ + j)*3 + 2];
        float o = 0.0f;
        if (v > 0.0f) {
            float sg = 2.0f * s_sig[j];
            float denom = fmaxf(2.0f * sg * sg * area_ks, 1e-6f);
            float scale = -LOG2E / denom;
            float2 cxy = s_xy[j][g];
            float dx = cxy.x - kx;
            float dy = cxy.y - ky;
            o = fast_ex2(fmaf(dx, dx, dy*dy) * scale);
        }
        s_val[g*JJ + j] = o;
    }
    __syncthreads();

    // ---- Phase E: emit outputs (vectorized parts store; s_val now 16B aligned) ----
    {
        float4* parts4 = (float4*)(out + (size_t)(b*CC + c) * GG * JJ);
        const float4* sv4 = (const float4*)s_val;
        for (int idx = tid; idx < (GG*JJ)/4; idx += NTHR) parts4[idx] = sv4[idx];
    }

    float* person = out + PERSON_OFF + (size_t)(b*CC + c) * GG;
    const float ivs_ks = s_ivs[ks];
    for (int g = tid; g < GG; g += NTHR) {
        float s = 0.f;
        #pragma unroll
        for (int j = 0; j < JJ; j++) s += s_val[g*JJ + j];
        person[g] = s * ivs_ks;
    }

    if (tid < JJ) {
        int j = tid;
        float X = kpt[(ks*JJ + j)*3 + 0];
        float Y = kpt[(ks*JJ + j)*3 + 1];
        float V = kpt[(ks*JJ + j)*3 + 2];
        float t00 = transforms[b*9+0], t01 = transforms[b*9+1], t02 = transforms[b*9+2];
        float t10 = transforms[b*9+3], t11 = transforms[b*9+4], t12 = transforms[b*9+5];
        float gx = t00*X + t01*Y + t02;
        float gy = t10*X + t11*Y + t12;
        if (flip) gx = WIDTH_F - 1.0f - gx;
        float sg = 2.0f * s_sig[j];
        float gv = (V > 0.f) ? (t00 * t11) * (area_ks * sg * sg) : 0.0f;
        float* pg = out + POSE_OFF + (size_t)((b*CC + c)*JJ + j) * 3;
        pg[0] = gx; pg[1] = gy; pg[2] = gv;
    }
}

extern "C" void kernel_launch(void* const* d_in, const int* in_sizes, int n_in,
                              void* d_out, int out_size) {
    const float* pose_pool  = (const float*)d_in[0];
    const float* keypoints  = (const float*)d_in[1];
    const float* areas      = (const float*)d_in[2];
    const float* transforms = (const float*)d_in[3];
    const float* tinv       = (const float*)d_in[4];
    const int*   hflip      = (const int*)  d_in[5];
    const float* sigmas     = (const float*)d_in[6];
    float* out = (float*)d_out;

    dim3 grid(CC, BB);
    oks_assign_kernel<<<grid, NTHR>>>(pose_pool, keypoints, areas, transforms,
                                      tinv, hflip, sigmas, out);
}